// round 7
// baseline (speedup 1.0000x reference)
#include <cuda_runtime.h>
#include <cuda_bf16.h>
#include <math.h>
#include <stdint.h>

// ---------------------------------------------------------------------------
// DynamicWeightProjection  (BT=4096, D=4096) — mma.sync bf16x3 version
//
// tcgen05 is unusable here (harness PTX target is sm_103 without the 'a'
// suffix), so tensor work goes through baseline mma.sync.m16n8k16.bf16.
//
//   convert:  X -> Xhi/Xlo bf16 ; [dw1|dd]^T -> Whi/Wlo [640][4096]
//             qkw^T -> Qhi/Qlo [4][2048][128]
//   GEMM1  :  (Xhi+Xlo)(Whi+Wlo) ~ hi*hi + hi*lo + lo*hi  (fp32 acc)
//             epilogue: gelu -> g_Hhi/g_Hlo (bf16 split), tanh -> dd outputs
//   GEMM2  :  H_c @ qkw_c  (bf16x3), epilogue RMS-norm on w1 half
//   KW     :  per-token 32x32 kw1^T kw2 + diag(kdd)
// ---------------------------------------------------------------------------

#define BT 4096
#define DDIM 4096

#define OFF_PRE_QW1   0ul
#define OFF_PRE_QW2   4194304ul
#define OFF_PRE_KW1   8388608ul
#define OFF_PRE_KW2   12582912ul
#define OFF_PRE_QDD   16777216ul
#define OFF_PRE_KDD   16908288ul
#define OFF_POST_QW1  17039360ul
#define OFF_POST_QW2  21233664ul
#define OFF_POST_KW1  25427968ul
#define OFF_POST_KW2  29622272ul
#define OFF_POST_QDD  33816576ul
#define OFF_POST_KDD  33947648ul
#define OFF_KW        34078720ul

__device__ __align__(128) __nv_bfloat16 g_Xhi[BT * DDIM];
__device__ __align__(128) __nv_bfloat16 g_Xlo[BT * DDIM];
__device__ __align__(128) __nv_bfloat16 g_Whi[640 * DDIM];
__device__ __align__(128) __nv_bfloat16 g_Wlo[640 * DDIM];
__device__ __align__(128) __nv_bfloat16 g_Hhi[BT * 512];
__device__ __align__(128) __nv_bfloat16 g_Hlo[BT * 512];
__device__ __align__(128) __nv_bfloat16 g_Qhi[4 * 2048 * 128];
__device__ __align__(128) __nv_bfloat16 g_Qlo[4 * 2048 * 128];

__constant__ unsigned long c_ddoff[4] = {OFF_PRE_QDD, OFF_PRE_KDD, OFF_POST_QDD, OFF_POST_KDD};
__constant__ unsigned long c_w1off[4] = {OFF_PRE_QW1, OFF_PRE_KW1, OFF_POST_QW1, OFF_POST_KW1};
__constant__ unsigned long c_w2off[4] = {OFF_PRE_QW2, OFF_PRE_KW2, OFF_POST_QW2, OFF_POST_KW2};

// ===========================================================================
// PTX helpers (sm_80-level only — no arch-suffix features)
// ===========================================================================
__device__ __forceinline__ uint32_t smem_u32(const void* p) {
    uint32_t a;
    asm("{ .reg .u64 t; cvta.to.shared.u64 t, %1; cvt.u32.u64 %0, t; }"
        : "=r"(a) : "l"(p));
    return a;
}

#define CP_ASYNC16(dst, src) \
    asm volatile("cp.async.cg.shared.global [%0], [%1], 16;" :: "r"(dst), "l"(src))
#define CP_COMMIT() asm volatile("cp.async.commit_group;" ::: "memory")
#define CP_WAIT(n)  asm volatile("cp.async.wait_group %0;" :: "n"(n) : "memory")

// D += A * B  (m16n8k16, bf16 in, fp32 acc)
#define MMA_BF16(d, a, b) \
    asm volatile("mma.sync.aligned.m16n8k16.row.col.f32.bf16.bf16.f32 " \
        "{%0,%1,%2,%3}, {%4,%5,%6,%7}, {%8,%9}, {%0,%1,%2,%3};" \
        : "+f"((d)[0]), "+f"((d)[1]), "+f"((d)[2]), "+f"((d)[3]) \
        : "r"((a)[0]), "r"((a)[1]), "r"((a)[2]), "r"((a)[3]), \
          "r"((b)[0]), "r"((b)[1]))

// SMEM tile geometry (shared by both GEMMs):
//   A: 128 rows x 64 k (bf16), row stride 144 B (72 elems) -> conflict-free
//   layout per stage: [A_hi 18432][A_lo 18432][B_hi 18432][B_lo 18432]
#define RSTRIDE 144
#define OFF_ALO 18432
#define OFF_BHI 36864
#define OFF_BLO 55296
#define STAGE   73728
#define SMEM_TOTAL (2 * STAGE)   // 147456

// ===========================================================================
// Conversion kernels
// ===========================================================================
__global__ void __launch_bounds__(256) convert_x_kernel(const float* __restrict__ X)
{
    size_t i = ((size_t)blockIdx.x * 256 + threadIdx.x) * 4;
    float4 v = *(const float4*)(X + i);
    __nv_bfloat16 h0 = __float2bfloat16_rn(v.x);
    __nv_bfloat16 h1 = __float2bfloat16_rn(v.y);
    __nv_bfloat16 h2 = __float2bfloat16_rn(v.z);
    __nv_bfloat16 h3 = __float2bfloat16_rn(v.w);
    __nv_bfloat16 l0 = __float2bfloat16_rn(v.x - __bfloat162float(h0));
    __nv_bfloat16 l1 = __float2bfloat16_rn(v.y - __bfloat162float(h1));
    __nv_bfloat16 l2 = __float2bfloat16_rn(v.z - __bfloat162float(h2));
    __nv_bfloat16 l3 = __float2bfloat16_rn(v.w - __bfloat162float(h3));
    uint2 uh, ul;
    uh.x = (uint32_t)__bfloat16_as_ushort(h0) | ((uint32_t)__bfloat16_as_ushort(h1) << 16);
    uh.y = (uint32_t)__bfloat16_as_ushort(h2) | ((uint32_t)__bfloat16_as_ushort(h3) << 16);
    ul.x = (uint32_t)__bfloat16_as_ushort(l0) | ((uint32_t)__bfloat16_as_ushort(l1) << 16);
    ul.y = (uint32_t)__bfloat16_as_ushort(l2) | ((uint32_t)__bfloat16_as_ushort(l3) << 16);
    *(uint2*)(g_Xhi + i) = uh;
    *(uint2*)(g_Xlo + i) = ul;
}

// [dw1 | dd] (K-major [4096][640]) -> W^T [640][4096] bf16 hi/lo
__global__ void convert_w_kernel(const float* __restrict__ dw1, const float* __restrict__ dd)
{
    __shared__ float t[32][33];
    const int n0 = blockIdx.x * 32;
    const int k0 = blockIdx.y * 32;
    const int tx = threadIdx.x, ty = threadIdx.y;
    #pragma unroll
    for (int r = 0; r < 4; r++) {
        int k = k0 + ty + r * 8;
        int n = n0 + tx;
        float v = (n < 512) ? dw1[(size_t)k * 512 + n] : dd[(size_t)k * 128 + (n - 512)];
        t[ty + r * 8][tx] = v;
    }
    __syncthreads();
    #pragma unroll
    for (int r = 0; r < 4; r++) {
        int n = n0 + ty + r * 8;
        int k = k0 + tx;
        float v = t[tx][ty + r * 8];
        __nv_bfloat16 h = __float2bfloat16_rn(v);
        g_Whi[(size_t)n * 4096 + k] = h;
        g_Wlo[(size_t)n * 4096 + k] = __float2bfloat16_rn(v - __bfloat162float(h));
    }
}

// qkw (c,[128][2048]) -> Q^T [c][2048][128] bf16 hi/lo
__global__ void convert_q_kernel(const float* __restrict__ qkw)
{
    __shared__ float t[32][33];
    const int n0 = blockIdx.x * 32;
    const int k0 = blockIdx.y * 32;
    const int c  = blockIdx.z;
    const int tx = threadIdx.x, ty = threadIdx.y;
    #pragma unroll
    for (int r = 0; r < 4; r++) {
        int k = k0 + ty + r * 8;
        int n = n0 + tx;
        t[ty + r * 8][tx] = qkw[((size_t)c * 128 + k) * 2048 + n];
    }
    __syncthreads();
    #pragma unroll
    for (int r = 0; r < 4; r++) {
        int n = n0 + ty + r * 8;
        int k = k0 + tx;
        float v = t[tx][ty + r * 8];
        __nv_bfloat16 h = __float2bfloat16_rn(v);
        size_t o = ((size_t)c * 2048 + n) * 128 + k;
        g_Qhi[o] = h;
        g_Qlo[o] = __float2bfloat16_rn(v - __bfloat162float(h));
    }
}

// ===========================================================================
// Shared GEMM building blocks
// ===========================================================================
// Load one 128x64(A) + 128x64(B) hi/lo stage via cp.async (256 threads).
__device__ __forceinline__ void load_stage(
    int tid, uint32_t sb,
    const __nv_bfloat16* __restrict__ Ah, const __nv_bfloat16* __restrict__ Al, size_t lda,
    const __nv_bfloat16* __restrict__ Bh, const __nv_bfloat16* __restrict__ Bl, size_t ldb)
{
    #pragma unroll
    for (int i = 0; i < 4; i++) {
        const int idx = tid + i * 256;
        const int row = idx >> 3, cc = idx & 7;
        const uint32_t d = sb + row * RSTRIDE + cc * 16;
        const char* pa = (const char*)(Ah + (size_t)row * lda) + cc * 16;
        const char* qa = (const char*)(Al + (size_t)row * lda) + cc * 16;
        const char* pb = (const char*)(Bh + (size_t)row * ldb) + cc * 16;
        const char* qb = (const char*)(Bl + (size_t)row * ldb) + cc * 16;
        CP_ASYNC16(d,           pa);
        CP_ASYNC16(d + OFF_ALO, qa);
        CP_ASYNC16(d + OFF_BHI, pb);
        CP_ASYNC16(d + OFF_BLO, qb);
    }
}

// Compute one BK=64 chunk: per warp m64 x n32, bf16x3 (hi*hi + hi*lo + lo*hi).
__device__ __forceinline__ void compute_chunk(
    const char* s, int wm, int wn, int gid, int tig, float acc[4][4][4])
{
    #pragma unroll
    for (int ks = 0; ks < 4; ks++) {
        const int co = ks * 32 + tig * 4;
        uint32_t ah[4][4], al[4][4];
        #pragma unroll
        for (int mt = 0; mt < 4; mt++) {
            const char* p = s + (wm * 64 + mt * 16 + gid) * RSTRIDE + co;
            ah[mt][0] = *(const uint32_t*)(p);
            ah[mt][1] = *(const uint32_t*)(p + 8 * RSTRIDE);
            ah[mt][2] = *(const uint32_t*)(p + 16);
            ah[mt][3] = *(const uint32_t*)(p + 8 * RSTRIDE + 16);
            const char* q = p + OFF_ALO;
            al[mt][0] = *(const uint32_t*)(q);
            al[mt][1] = *(const uint32_t*)(q + 8 * RSTRIDE);
            al[mt][2] = *(const uint32_t*)(q + 16);
            al[mt][3] = *(const uint32_t*)(q + 8 * RSTRIDE + 16);
        }
        uint32_t bh[4][2], bl[4][2];
        #pragma unroll
        for (int nt = 0; nt < 4; nt++) {
            const char* p = s + OFF_BHI + (wn * 32 + nt * 8 + gid) * RSTRIDE + co;
            bh[nt][0] = *(const uint32_t*)(p);
            bh[nt][1] = *(const uint32_t*)(p + 16);
            bl[nt][0] = *(const uint32_t*)(p + (OFF_BLO - OFF_BHI));
            bl[nt][1] = *(const uint32_t*)(p + (OFF_BLO - OFF_BHI) + 16);
        }
        #pragma unroll
        for (int mt = 0; mt < 4; mt++)
            #pragma unroll
            for (int nt = 0; nt < 4; nt++) {
                MMA_BF16(acc[mt][nt], ah[mt], bh[nt]);
                MMA_BF16(acc[mt][nt], ah[mt], bl[nt]);
                MMA_BF16(acc[mt][nt], al[mt], bh[nt]);
            }
    }
}

// ===========================================================================
// GEMM1: X(4096x4096) @ W^T cols (640), tile 128x128, grid (5, 32)
// ===========================================================================
__global__ void __launch_bounds__(256) gemm1_mma(float* __restrict__ out)
{
    extern __shared__ char dyn[];
    const int tid = threadIdx.x;
    const int wid = tid >> 5, lane = tid & 31;
    const int gid = lane >> 2, tig = lane & 3;
    const int wm = wid >> 2, wn = wid & 3;
    const int n0 = blockIdx.x * 128;
    const int m0 = blockIdx.y * 128;
    const uint32_t sb = smem_u32(dyn);

    float acc[4][4][4];
    #pragma unroll
    for (int mt = 0; mt < 4; mt++)
        #pragma unroll
        for (int nt = 0; nt < 4; nt++)
            #pragma unroll
            for (int e = 0; e < 4; e++) acc[mt][nt][e] = 0.f;

    load_stage(tid, sb,
               g_Xhi + (size_t)m0 * DDIM, g_Xlo + (size_t)m0 * DDIM, DDIM,
               g_Whi + (size_t)n0 * DDIM, g_Wlo + (size_t)n0 * DDIM, DDIM);
    CP_COMMIT();

    const int KC = DDIM / 64;   // 64
    for (int kc = 0; kc < KC; kc++) {
        const int buf = kc & 1;
        if (kc + 1 < KC) {
            const int kb = (kc + 1) * 64;
            load_stage(tid, sb + (buf ^ 1) * STAGE,
                       g_Xhi + (size_t)m0 * DDIM + kb, g_Xlo + (size_t)m0 * DDIM + kb, DDIM,
                       g_Whi + (size_t)n0 * DDIM + kb, g_Wlo + (size_t)n0 * DDIM + kb, DDIM);
            CP_COMMIT();
            CP_WAIT(1);
        } else {
            CP_WAIT(0);
        }
        __syncthreads();
        compute_chunk(dyn + buf * STAGE, wm, wn, gid, tig, acc);
        __syncthreads();
    }

    // epilogue
    if (blockIdx.x < 4) {
        // gelu -> g_Hhi / g_Hlo (bf16 split)
        #pragma unroll
        for (int mt = 0; mt < 4; mt++) {
            const int r0 = m0 + wm * 64 + mt * 16 + gid;
            #pragma unroll
            for (int nt = 0; nt < 4; nt++) {
                const int col = n0 + wn * 32 + nt * 8 + tig * 2;
                #pragma unroll
                for (int half = 0; half < 2; half++) {
                    const int r = r0 + half * 8;
                    const float v0 = acc[mt][nt][half * 2 + 0];
                    const float v1 = acc[mt][nt][half * 2 + 1];
                    const float g0 = 0.5f * v0 * (1.0f + erff(v0 * 0.70710678118654752f));
                    const float g1 = 0.5f * v1 * (1.0f + erff(v1 * 0.70710678118654752f));
                    __nv_bfloat16 h0 = __float2bfloat16_rn(g0);
                    __nv_bfloat16 h1 = __float2bfloat16_rn(g1);
                    __nv_bfloat16 l0 = __float2bfloat16_rn(g0 - __bfloat162float(h0));
                    __nv_bfloat16 l1 = __float2bfloat16_rn(g1 - __bfloat162float(h1));
                    uint32_t ph = (uint32_t)__bfloat16_as_ushort(h0) |
                                  ((uint32_t)__bfloat16_as_ushort(h1) << 16);
                    uint32_t pl = (uint32_t)__bfloat16_as_ushort(l0) |
                                  ((uint32_t)__bfloat16_as_ushort(l1) << 16);
                    *(uint32_t*)(g_Hhi + (size_t)r * 512 + col) = ph;
                    *(uint32_t*)(g_Hlo + (size_t)r * 512 + col) = pl;
                }
            }
        }
    } else {
        // tanh -> the four *dd outputs; group index within this tile = wn
        const size_t base = c_ddoff[wn];
        #pragma unroll
        for (int mt = 0; mt < 4; mt++) {
            const int r0 = m0 + wm * 64 + mt * 16 + gid;
            #pragma unroll
            for (int nt = 0; nt < 4; nt++) {
                const int cl = nt * 8 + tig * 2;
                #pragma unroll
                for (int half = 0; half < 2; half++) {
                    const int r = r0 + half * 8;
                    float2 o;
                    o.x = tanhf(acc[mt][nt][half * 2 + 0]);
                    o.y = tanhf(acc[mt][nt][half * 2 + 1]);
                    *(float2*)(out + base + (size_t)r * 32 + cl) = o;
                }
            }
        }
    }
}

// ===========================================================================
// GEMM2: per c: H_c(4096x128) @ qkw_c(128x2048); tile 128x128, grid (16,32,4)
// ===========================================================================
__global__ void __launch_bounds__(256) gemm2_mma(float* __restrict__ out)
{
    extern __shared__ char dyn[];
    const int tid = threadIdx.x;
    const int wid = tid >> 5, lane = tid & 31;
    const int gid = lane >> 2, tig = lane & 3;
    const int wm = wid >> 2, wn = wid & 3;
    const int n0 = blockIdx.x * 128;
    const int m0 = blockIdx.y * 128;
    const int c  = blockIdx.z;
    const uint32_t sb = smem_u32(dyn);

    const __nv_bfloat16* Ah = g_Hhi + (size_t)m0 * 512 + c * 128;
    const __nv_bfloat16* Al = g_Hlo + (size_t)m0 * 512 + c * 128;
    const __nv_bfloat16* Bh = g_Qhi + ((size_t)c * 2048 + n0) * 128;
    const __nv_bfloat16* Bl = g_Qlo + ((size_t)c * 2048 + n0) * 128;

    float acc[4][4][4];
    #pragma unroll
    for (int mt = 0; mt < 4; mt++)
        #pragma unroll
        for (int nt = 0; nt < 4; nt++)
            #pragma unroll
            for (int e = 0; e < 4; e++) acc[mt][nt][e] = 0.f;

    load_stage(tid, sb, Ah, Al, 512, Bh, Bl, 128);
    CP_COMMIT();
    load_stage(tid, sb + STAGE, Ah + 64, Al + 64, 512, Bh + 64, Bl + 64, 128);
    CP_COMMIT();

    CP_WAIT(1);
    __syncthreads();
    compute_chunk(dyn, wm, wn, gid, tig, acc);
    CP_WAIT(0);
    __syncthreads();
    compute_chunk(dyn + STAGE, wm, wn, gid, tig, acc);

    // epilogue: RMS over the 32-wide n-group (= exactly this warp's n range)
    const bool is_w1 = (n0 < 1024);
    const size_t base = is_w1 ? c_w1off[c] : c_w2off[c];
    const int ncol = (is_w1 ? n0 : n0 - 1024) + wn * 32;

    #pragma unroll
    for (int mt = 0; mt < 4; mt++) {
        float ss0 = 0.f, ss1 = 0.f;
        #pragma unroll
        for (int nt = 0; nt < 4; nt++) {
            ss0 = fmaf(acc[mt][nt][0], acc[mt][nt][0], ss0);
            ss0 = fmaf(acc[mt][nt][1], acc[mt][nt][1], ss0);
            ss1 = fmaf(acc[mt][nt][2], acc[mt][nt][2], ss1);
            ss1 = fmaf(acc[mt][nt][3], acc[mt][nt][3], ss1);
        }
        ss0 += __shfl_xor_sync(0xFFFFFFFFu, ss0, 1);
        ss0 += __shfl_xor_sync(0xFFFFFFFFu, ss0, 2);
        ss1 += __shfl_xor_sync(0xFFFFFFFFu, ss1, 1);
        ss1 += __shfl_xor_sync(0xFFFFFFFFu, ss1, 2);
        const float s0 = is_w1 ? rsqrtf(ss0 * (1.0f / 32.0f) + 1e-6f) : 1.0f;
        const float s1 = is_w1 ? rsqrtf(ss1 * (1.0f / 32.0f) + 1e-6f) : 1.0f;
        const int r0 = m0 + wm * 64 + mt * 16 + gid;
        #pragma unroll
        for (int nt = 0; nt < 4; nt++) {
            const int cl = ncol + nt * 8 + tig * 2;
            float2 o0, o1;
            o0.x = acc[mt][nt][0] * s0;  o0.y = acc[mt][nt][1] * s0;
            o1.x = acc[mt][nt][2] * s1;  o1.y = acc[mt][nt][3] * s1;
            *(float2*)(out + base + (size_t)r0 * 1024 + cl)       = o0;
            *(float2*)(out + base + (size_t)(r0 + 8) * 1024 + cl) = o1;
        }
    }
}

// ===========================================================================
// KW: per token, KW[p][m][n] = sum_i kw1[i][m]*kw2[i][n] + (m==n)*kdd[m]
// ===========================================================================
__global__ void __launch_bounds__(256) kw_kernel(float* __restrict__ out)
{
    __shared__ float a1[1024], b1[1024], a2[1024], b2[1024];
    __shared__ float d1[32], d2[32];

    const int t = blockIdx.x;
    const int tid = threadIdx.x;
    const size_t tb = (size_t)t * 1024;

    for (int i = tid; i < 1024; i += 256) {
        a1[i] = out[OFF_PRE_KW1  + tb + i];
        b1[i] = out[OFF_PRE_KW2  + tb + i];
        a2[i] = out[OFF_POST_KW1 + tb + i];
        b2[i] = out[OFF_POST_KW2 + tb + i];
    }
    if (tid < 32) {
        d1[tid] = out[OFF_PRE_KDD  + (size_t)t * 32 + tid];
        d2[tid] = out[OFF_POST_KDD + (size_t)t * 32 + tid];
    }
    __syncthreads();

    const size_t kwbase = OFF_KW + (size_t)t * 2048;
    #pragma unroll
    for (int q = 0; q < 4; q++) {
        const int o = tid + q * 256;
        const int m = o >> 5, n = o & 31;
        float s1 = 0.f, s2 = 0.f;
        #pragma unroll
        for (int i = 0; i < 32; i++) {
            s1 = fmaf(a1[i * 32 + m], b1[i * 32 + n], s1);
            s2 = fmaf(a2[i * 32 + m], b2[i * 32 + n], s2);
        }
        if (m == n) { s1 += d1[m]; s2 += d2[m]; }
        out[kwbase + o]        = s1;
        out[kwbase + 1024 + o] = s2;
    }
}

// ---------------------------------------------------------------------------
extern "C" void kernel_launch(void* const* d_in, const int* in_sizes, int n_in,
                              void* d_out, int out_size)
{
    const float* X   = (const float*)d_in[0];  // (4096, 4096)
    const float* dw1 = (const float*)d_in[1];  // (4096, 512)
    const float* qkw = (const float*)d_in[2];  // (4, 128, 2048)
    const float* dd  = (const float*)d_in[3];  // (4096, 128)
    float* out = (float*)d_out;
    (void)in_sizes; (void)n_in; (void)out_size;

    cudaFuncSetAttribute(gemm1_mma, cudaFuncAttributeMaxDynamicSharedMemorySize, SMEM_TOTAL);
    cudaFuncSetAttribute(gemm2_mma, cudaFuncAttributeMaxDynamicSharedMemorySize, SMEM_TOTAL);

    convert_x_kernel<<<16384, 256>>>(X);
    convert_w_kernel<<<dim3(20, 128), dim3(32, 8)>>>(dw1, dd);
    convert_q_kernel<<<dim3(64, 4, 4), dim3(32, 8)>>>(qkw);

    gemm1_mma<<<dim3(5, 32), 256, SMEM_TOTAL>>>(out);
    gemm2_mma<<<dim3(16, 32, 4), 256, SMEM_TOTAL>>>(out);
    kw_kernel<<<BT, 256>>>(out);
}

// round 8
// speedup vs baseline: 1.0007x; 1.0007x over previous
#include <cuda_runtime.h>
#include <cuda_bf16.h>
#include <math.h>
#include <stdint.h>

// ---------------------------------------------------------------------------
// DynamicWeightProjection  (BT=4096, D=4096) — mma.sync bf16x3 version
//
// tcgen05 is unusable here (harness PTX target is sm_103 without the 'a'
// suffix), so tensor work goes through baseline mma.sync.m16n8k16.bf16.
//
//   convert:  X -> Xhi/Xlo bf16 ; [dw1|dd]^T -> Whi/Wlo [640][4096]
//             qkw^T -> Qhi/Qlo [4][2048][128]
//   GEMM1  :  (Xhi+Xlo)(Whi+Wlo) ~ hi*hi + hi*lo + lo*hi  (fp32 acc)
//             epilogue: gelu -> g_Hhi/g_Hlo (bf16 split), tanh -> dd outputs
//   GEMM2  :  H_c @ qkw_c  (bf16x3), epilogue RMS-norm on w1 half
//   KW     :  per-token 32x32 kw1^T kw2 + diag(kdd)
// ---------------------------------------------------------------------------

#define BT 4096
#define DDIM 4096

#define OFF_PRE_QW1   0ul
#define OFF_PRE_QW2   4194304ul
#define OFF_PRE_KW1   8388608ul
#define OFF_PRE_KW2   12582912ul
#define OFF_PRE_QDD   16777216ul
#define OFF_PRE_KDD   16908288ul
#define OFF_POST_QW1  17039360ul
#define OFF_POST_QW2  21233664ul
#define OFF_POST_KW1  25427968ul
#define OFF_POST_KW2  29622272ul
#define OFF_POST_QDD  33816576ul
#define OFF_POST_KDD  33947648ul
#define OFF_KW        34078720ul

__device__ __align__(128) __nv_bfloat16 g_Xhi[BT * DDIM];
__device__ __align__(128) __nv_bfloat16 g_Xlo[BT * DDIM];
__device__ __align__(128) __nv_bfloat16 g_Whi[640 * DDIM];
__device__ __align__(128) __nv_bfloat16 g_Wlo[640 * DDIM];
__device__ __align__(128) __nv_bfloat16 g_Hhi[BT * 512];
__device__ __align__(128) __nv_bfloat16 g_Hlo[BT * 512];
__device__ __align__(128) __nv_bfloat16 g_Qhi[4 * 2048 * 128];
__device__ __align__(128) __nv_bfloat16 g_Qlo[4 * 2048 * 128];

__constant__ unsigned long c_ddoff[4] = {OFF_PRE_QDD, OFF_PRE_KDD, OFF_POST_QDD, OFF_POST_KDD};
__constant__ unsigned long c_w1off[4] = {OFF_PRE_QW1, OFF_PRE_KW1, OFF_POST_QW1, OFF_POST_KW1};
__constant__ unsigned long c_w2off[4] = {OFF_PRE_QW2, OFF_PRE_KW2, OFF_POST_QW2, OFF_POST_KW2};

// ===========================================================================
// PTX helpers (sm_80-level only — no arch-suffix features)
// ===========================================================================
__device__ __forceinline__ uint32_t smem_u32(const void* p) {
    uint32_t a;
    asm("{ .reg .u64 t; cvta.to.shared.u64 t, %1; cvt.u32.u64 %0, t; }"
        : "=r"(a) : "l"(p));
    return a;
}

#define CP_ASYNC16(dst, src) \
    asm volatile("cp.async.cg.shared.global [%0], [%1], 16;" :: "r"(dst), "l"(src))
#define CP_COMMIT() asm volatile("cp.async.commit_group;" ::: "memory")
#define CP_WAIT(n)  asm volatile("cp.async.wait_group %0;" :: "n"(n) : "memory")

// D += A * B  (m16n8k16, bf16 in, fp32 acc)
#define MMA_BF16(d, a, b) \
    asm volatile("mma.sync.aligned.m16n8k16.row.col.f32.bf16.bf16.f32 " \
        "{%0,%1,%2,%3}, {%4,%5,%6,%7}, {%8,%9}, {%0,%1,%2,%3};" \
        : "+f"((d)[0]), "+f"((d)[1]), "+f"((d)[2]), "+f"((d)[3]) \
        : "r"((a)[0]), "r"((a)[1]), "r"((a)[2]), "r"((a)[3]), \
          "r"((b)[0]), "r"((b)[1]))

// SMEM tile geometry (shared by both GEMMs):
//   A: 128 rows x 64 k (bf16), row stride 144 B (72 elems) -> conflict-free
//   layout per stage: [A_hi 18432][A_lo 18432][B_hi 18432][B_lo 18432]
#define RSTRIDE 144
#define OFF_ALO 18432
#define OFF_BHI 36864
#define OFF_BLO 55296
#define STAGE   73728
#define SMEM_TOTAL (2 * STAGE)   // 147456

// ===========================================================================
// Conversion kernels
// ===========================================================================
__global__ void __launch_bounds__(256) convert_x_kernel(const float* __restrict__ X)
{
    size_t i = ((size_t)blockIdx.x * 256 + threadIdx.x) * 4;
    float4 v = *(const float4*)(X + i);
    __nv_bfloat16 h0 = __float2bfloat16_rn(v.x);
    __nv_bfloat16 h1 = __float2bfloat16_rn(v.y);
    __nv_bfloat16 h2 = __float2bfloat16_rn(v.z);
    __nv_bfloat16 h3 = __float2bfloat16_rn(v.w);
    __nv_bfloat16 l0 = __float2bfloat16_rn(v.x - __bfloat162float(h0));
    __nv_bfloat16 l1 = __float2bfloat16_rn(v.y - __bfloat162float(h1));
    __nv_bfloat16 l2 = __float2bfloat16_rn(v.z - __bfloat162float(h2));
    __nv_bfloat16 l3 = __float2bfloat16_rn(v.w - __bfloat162float(h3));
    uint2 uh, ul;
    uh.x = (uint32_t)__bfloat16_as_ushort(h0) | ((uint32_t)__bfloat16_as_ushort(h1) << 16);
    uh.y = (uint32_t)__bfloat16_as_ushort(h2) | ((uint32_t)__bfloat16_as_ushort(h3) << 16);
    ul.x = (uint32_t)__bfloat16_as_ushort(l0) | ((uint32_t)__bfloat16_as_ushort(l1) << 16);
    ul.y = (uint32_t)__bfloat16_as_ushort(l2) | ((uint32_t)__bfloat16_as_ushort(l3) << 16);
    *(uint2*)(g_Xhi + i) = uh;
    *(uint2*)(g_Xlo + i) = ul;
}

// [dw1 | dd] (K-major [4096][640]) -> W^T [640][4096] bf16 hi/lo
__global__ void convert_w_kernel(const float* __restrict__ dw1, const float* __restrict__ dd)
{
    __shared__ float t[32][33];
    const int n0 = blockIdx.x * 32;
    const int k0 = blockIdx.y * 32;
    const int tx = threadIdx.x, ty = threadIdx.y;
    #pragma unroll
    for (int r = 0; r < 4; r++) {
        int k = k0 + ty + r * 8;
        int n = n0 + tx;
        float v = (n < 512) ? dw1[(size_t)k * 512 + n] : dd[(size_t)k * 128 + (n - 512)];
        t[ty + r * 8][tx] = v;
    }
    __syncthreads();
    #pragma unroll
    for (int r = 0; r < 4; r++) {
        int n = n0 + ty + r * 8;
        int k = k0 + tx;
        float v = t[tx][ty + r * 8];
        __nv_bfloat16 h = __float2bfloat16_rn(v);
        g_Whi[(size_t)n * 4096 + k] = h;
        g_Wlo[(size_t)n * 4096 + k] = __float2bfloat16_rn(v - __bfloat162float(h));
    }
}

// qkw (c,[128][2048]) -> Q^T [c][2048][128] bf16 hi/lo
__global__ void convert_q_kernel(const float* __restrict__ qkw)
{
    __shared__ float t[32][33];
    const int n0 = blockIdx.x * 32;
    const int k0 = blockIdx.y * 32;
    const int c  = blockIdx.z;
    const int tx = threadIdx.x, ty = threadIdx.y;
    #pragma unroll
    for (int r = 0; r < 4; r++) {
        int k = k0 + ty + r * 8;
        int n = n0 + tx;
        t[ty + r * 8][tx] = qkw[((size_t)c * 128 + k) * 2048 + n];
    }
    __syncthreads();
    #pragma unroll
    for (int r = 0; r < 4; r++) {
        int n = n0 + ty + r * 8;
        int k = k0 + tx;
        float v = t[tx][ty + r * 8];
        __nv_bfloat16 h = __float2bfloat16_rn(v);
        size_t o = ((size_t)c * 2048 + n) * 128 + k;
        g_Qhi[o] = h;
        g_Qlo[o] = __float2bfloat16_rn(v - __bfloat162float(h));
    }
}

// ===========================================================================
// Shared GEMM building blocks
// ===========================================================================
// Load one 128x64(A) + 128x64(B) hi/lo stage via cp.async (256 threads).
__device__ __forceinline__ void load_stage(
    int tid, uint32_t sb,
    const __nv_bfloat16* __restrict__ Ah, const __nv_bfloat16* __restrict__ Al, size_t lda,
    const __nv_bfloat16* __restrict__ Bh, const __nv_bfloat16* __restrict__ Bl, size_t ldb)
{
    #pragma unroll
    for (int i = 0; i < 4; i++) {
        const int idx = tid + i * 256;
        const int row = idx >> 3, cc = idx & 7;
        const uint32_t d = sb + row * RSTRIDE + cc * 16;
        const char* pa = (const char*)(Ah + (size_t)row * lda) + cc * 16;
        const char* qa = (const char*)(Al + (size_t)row * lda) + cc * 16;
        const char* pb = (const char*)(Bh + (size_t)row * ldb) + cc * 16;
        const char* qb = (const char*)(Bl + (size_t)row * ldb) + cc * 16;
        CP_ASYNC16(d,           pa);
        CP_ASYNC16(d + OFF_ALO, qa);
        CP_ASYNC16(d + OFF_BHI, pb);
        CP_ASYNC16(d + OFF_BLO, qb);
    }
}

// Compute one BK=64 chunk: per warp m64 x n32, bf16x3 (hi*hi + hi*lo + lo*hi).
__device__ __forceinline__ void compute_chunk(
    const char* s, int wm, int wn, int gid, int tig, float acc[4][4][4])
{
    #pragma unroll
    for (int ks = 0; ks < 4; ks++) {
        const int co = ks * 32 + tig * 4;
        uint32_t ah[4][4], al[4][4];
        #pragma unroll
        for (int mt = 0; mt < 4; mt++) {
            const char* p = s + (wm * 64 + mt * 16 + gid) * RSTRIDE + co;
            ah[mt][0] = *(const uint32_t*)(p);
            ah[mt][1] = *(const uint32_t*)(p + 8 * RSTRIDE);
            ah[mt][2] = *(const uint32_t*)(p + 16);
            ah[mt][3] = *(const uint32_t*)(p + 8 * RSTRIDE + 16);
            const char* q = p + OFF_ALO;
            al[mt][0] = *(const uint32_t*)(q);
            al[mt][1] = *(const uint32_t*)(q + 8 * RSTRIDE);
            al[mt][2] = *(const uint32_t*)(q + 16);
            al[mt][3] = *(const uint32_t*)(q + 8 * RSTRIDE + 16);
        }
        uint32_t bh[4][2], bl[4][2];
        #pragma unroll
        for (int nt = 0; nt < 4; nt++) {
            const char* p = s + OFF_BHI + (wn * 32 + nt * 8 + gid) * RSTRIDE + co;
            bh[nt][0] = *(const uint32_t*)(p);
            bh[nt][1] = *(const uint32_t*)(p + 16);
            bl[nt][0] = *(const uint32_t*)(p + (OFF_BLO - OFF_BHI));
            bl[nt][1] = *(const uint32_t*)(p + (OFF_BLO - OFF_BHI) + 16);
        }
        #pragma unroll
        for (int mt = 0; mt < 4; mt++)
            #pragma unroll
            for (int nt = 0; nt < 4; nt++) {
                MMA_BF16(acc[mt][nt], ah[mt], bh[nt]);
                MMA_BF16(acc[mt][nt], ah[mt], bl[nt]);
                MMA_BF16(acc[mt][nt], al[mt], bh[nt]);
            }
    }
}

// ===========================================================================
// GEMM1: X(4096x4096) @ W^T cols (640), tile 128x128, grid (5, 32)
// ===========================================================================
__global__ void __launch_bounds__(256) gemm1_mma(float* __restrict__ out)
{
    extern __shared__ char dyn[];
    const int tid = threadIdx.x;
    const int wid = tid >> 5, lane = tid & 31;
    const int gid = lane >> 2, tig = lane & 3;
    const int wm = wid >> 2, wn = wid & 3;
    const int n0 = blockIdx.x * 128;
    const int m0 = blockIdx.y * 128;
    const uint32_t sb = smem_u32(dyn);

    float acc[4][4][4];
    #pragma unroll
    for (int mt = 0; mt < 4; mt++)
        #pragma unroll
        for (int nt = 0; nt < 4; nt++)
            #pragma unroll
            for (int e = 0; e < 4; e++) acc[mt][nt][e] = 0.f;

    load_stage(tid, sb,
               g_Xhi + (size_t)m0 * DDIM, g_Xlo + (size_t)m0 * DDIM, DDIM,
               g_Whi + (size_t)n0 * DDIM, g_Wlo + (size_t)n0 * DDIM, DDIM);
    CP_COMMIT();

    const int KC = DDIM / 64;   // 64
    for (int kc = 0; kc < KC; kc++) {
        const int buf = kc & 1;
        if (kc + 1 < KC) {
            const int kb = (kc + 1) * 64;
            load_stage(tid, sb + (buf ^ 1) * STAGE,
                       g_Xhi + (size_t)m0 * DDIM + kb, g_Xlo + (size_t)m0 * DDIM + kb, DDIM,
                       g_Whi + (size_t)n0 * DDIM + kb, g_Wlo + (size_t)n0 * DDIM + kb, DDIM);
            CP_COMMIT();
            CP_WAIT(1);
        } else {
            CP_WAIT(0);
        }
        __syncthreads();
        compute_chunk(dyn + buf * STAGE, wm, wn, gid, tig, acc);
        __syncthreads();
    }

    // epilogue
    if (blockIdx.x < 4) {
        // gelu -> g_Hhi / g_Hlo (bf16 split)
        #pragma unroll
        for (int mt = 0; mt < 4; mt++) {
            const int r0 = m0 + wm * 64 + mt * 16 + gid;
            #pragma unroll
            for (int nt = 0; nt < 4; nt++) {
                const int col = n0 + wn * 32 + nt * 8 + tig * 2;
                #pragma unroll
                for (int half = 0; half < 2; half++) {
                    const int r = r0 + half * 8;
                    const float v0 = acc[mt][nt][half * 2 + 0];
                    const float v1 = acc[mt][nt][half * 2 + 1];
                    const float g0 = 0.5f * v0 * (1.0f + erff(v0 * 0.70710678118654752f));
                    const float g1 = 0.5f * v1 * (1.0f + erff(v1 * 0.70710678118654752f));
                    __nv_bfloat16 h0 = __float2bfloat16_rn(g0);
                    __nv_bfloat16 h1 = __float2bfloat16_rn(g1);
                    __nv_bfloat16 l0 = __float2bfloat16_rn(g0 - __bfloat162float(h0));
                    __nv_bfloat16 l1 = __float2bfloat16_rn(g1 - __bfloat162float(h1));
                    uint32_t ph = (uint32_t)__bfloat16_as_ushort(h0) |
                                  ((uint32_t)__bfloat16_as_ushort(h1) << 16);
                    uint32_t pl = (uint32_t)__bfloat16_as_ushort(l0) |
                                  ((uint32_t)__bfloat16_as_ushort(l1) << 16);
                    *(uint32_t*)(g_Hhi + (size_t)r * 512 + col) = ph;
                    *(uint32_t*)(g_Hlo + (size_t)r * 512 + col) = pl;
                }
            }
        }
    } else {
        // tanh -> the four *dd outputs; group index within this tile = wn
        const size_t base = c_ddoff[wn];
        #pragma unroll
        for (int mt = 0; mt < 4; mt++) {
            const int r0 = m0 + wm * 64 + mt * 16 + gid;
            #pragma unroll
            for (int nt = 0; nt < 4; nt++) {
                const int cl = nt * 8 + tig * 2;
                #pragma unroll
                for (int half = 0; half < 2; half++) {
                    const int r = r0 + half * 8;
                    float2 o;
                    o.x = tanhf(acc[mt][nt][half * 2 + 0]);
                    o.y = tanhf(acc[mt][nt][half * 2 + 1]);
                    *(float2*)(out + base + (size_t)r * 32 + cl) = o;
                }
            }
        }
    }
}

// ===========================================================================
// GEMM2: per c: H_c(4096x128) @ qkw_c(128x2048); tile 128x128, grid (16,32,4)
// ===========================================================================
__global__ void __launch_bounds__(256) gemm2_mma(float* __restrict__ out)
{
    extern __shared__ char dyn[];
    const int tid = threadIdx.x;
    const int wid = tid >> 5, lane = tid & 31;
    const int gid = lane >> 2, tig = lane & 3;
    const int wm = wid >> 2, wn = wid & 3;
    const int n0 = blockIdx.x * 128;
    const int m0 = blockIdx.y * 128;
    const int c  = blockIdx.z;
    const uint32_t sb = smem_u32(dyn);

    const __nv_bfloat16* Ah = g_Hhi + (size_t)m0 * 512 + c * 128;
    const __nv_bfloat16* Al = g_Hlo + (size_t)m0 * 512 + c * 128;
    const __nv_bfloat16* Bh = g_Qhi + ((size_t)c * 2048 + n0) * 128;
    const __nv_bfloat16* Bl = g_Qlo + ((size_t)c * 2048 + n0) * 128;

    float acc[4][4][4];
    #pragma unroll
    for (int mt = 0; mt < 4; mt++)
        #pragma unroll
        for (int nt = 0; nt < 4; nt++)
            #pragma unroll
            for (int e = 0; e < 4; e++) acc[mt][nt][e] = 0.f;

    load_stage(tid, sb, Ah, Al, 512, Bh, Bl, 128);
    CP_COMMIT();
    load_stage(tid, sb + STAGE, Ah + 64, Al + 64, 512, Bh + 64, Bl + 64, 128);
    CP_COMMIT();

    CP_WAIT(1);
    __syncthreads();
    compute_chunk(dyn, wm, wn, gid, tig, acc);
    CP_WAIT(0);
    __syncthreads();
    compute_chunk(dyn + STAGE, wm, wn, gid, tig, acc);

    // epilogue: RMS over the 32-wide n-group (= exactly this warp's n range)
    const bool is_w1 = (n0 < 1024);
    const size_t base = is_w1 ? c_w1off[c] : c_w2off[c];
    const int ncol = (is_w1 ? n0 : n0 - 1024) + wn * 32;

    #pragma unroll
    for (int mt = 0; mt < 4; mt++) {
        float ss0 = 0.f, ss1 = 0.f;
        #pragma unroll
        for (int nt = 0; nt < 4; nt++) {
            ss0 = fmaf(acc[mt][nt][0], acc[mt][nt][0], ss0);
            ss0 = fmaf(acc[mt][nt][1], acc[mt][nt][1], ss0);
            ss1 = fmaf(acc[mt][nt][2], acc[mt][nt][2], ss1);
            ss1 = fmaf(acc[mt][nt][3], acc[mt][nt][3], ss1);
        }
        ss0 += __shfl_xor_sync(0xFFFFFFFFu, ss0, 1);
        ss0 += __shfl_xor_sync(0xFFFFFFFFu, ss0, 2);
        ss1 += __shfl_xor_sync(0xFFFFFFFFu, ss1, 1);
        ss1 += __shfl_xor_sync(0xFFFFFFFFu, ss1, 2);
        const float s0 = is_w1 ? rsqrtf(ss0 * (1.0f / 32.0f) + 1e-6f) : 1.0f;
        const float s1 = is_w1 ? rsqrtf(ss1 * (1.0f / 32.0f) + 1e-6f) : 1.0f;
        const int r0 = m0 + wm * 64 + mt * 16 + gid;
        #pragma unroll
        for (int nt = 0; nt < 4; nt++) {
            const int cl = ncol + nt * 8 + tig * 2;
            float2 o0, o1;
            o0.x = acc[mt][nt][0] * s0;  o0.y = acc[mt][nt][1] * s0;
            o1.x = acc[mt][nt][2] * s1;  o1.y = acc[mt][nt][3] * s1;
            *(float2*)(out + base + (size_t)r0 * 1024 + cl)       = o0;
            *(float2*)(out + base + (size_t)(r0 + 8) * 1024 + cl) = o1;
        }
    }
}

// ===========================================================================
// KW: per token, KW[p][m][n] = sum_i kw1[i][m]*kw2[i][n] + (m==n)*kdd[m]
// ===========================================================================
__global__ void __launch_bounds__(256) kw_kernel(float* __restrict__ out)
{
    __shared__ float a1[1024], b1[1024], a2[1024], b2[1024];
    __shared__ float d1[32], d2[32];

    const int t = blockIdx.x;
    const int tid = threadIdx.x;
    const size_t tb = (size_t)t * 1024;

    for (int i = tid; i < 1024; i += 256) {
        a1[i] = out[OFF_PRE_KW1  + tb + i];
        b1[i] = out[OFF_PRE_KW2  + tb + i];
        a2[i] = out[OFF_POST_KW1 + tb + i];
        b2[i] = out[OFF_POST_KW2 + tb + i];
    }
    if (tid < 32) {
        d1[tid] = out[OFF_PRE_KDD  + (size_t)t * 32 + tid];
        d2[tid] = out[OFF_POST_KDD + (size_t)t * 32 + tid];
    }
    __syncthreads();

    const size_t kwbase = OFF_KW + (size_t)t * 2048;
    #pragma unroll
    for (int q = 0; q < 4; q++) {
        const int o = tid + q * 256;
        const int m = o >> 5, n = o & 31;
        float s1 = 0.f, s2 = 0.f;
        #pragma unroll
        for (int i = 0; i < 32; i++) {
            s1 = fmaf(a1[i * 32 + m], b1[i * 32 + n], s1);
            s2 = fmaf(a2[i * 32 + m], b2[i * 32 + n], s2);
        }
        if (m == n) { s1 += d1[m]; s2 += d2[m]; }
        out[kwbase + o]        = s1;
        out[kwbase + 1024 + o] = s2;
    }
}

// ---------------------------------------------------------------------------
extern "C" void kernel_launch(void* const* d_in, const int* in_sizes, int n_in,
                              void* d_out, int out_size)
{
    const float* X   = (const float*)d_in[0];  // (4096, 4096)
    const float* dw1 = (const float*)d_in[1];  // (4096, 512)
    const float* qkw = (const float*)d_in[2];  // (4, 128, 2048)
    const float* dd  = (const float*)d_in[3];  // (4096, 128)
    float* out = (float*)d_out;
    (void)in_sizes; (void)n_in; (void)out_size;

    cudaFuncSetAttribute(gemm1_mma, cudaFuncAttributeMaxDynamicSharedMemorySize, SMEM_TOTAL);
    cudaFuncSetAttribute(gemm2_mma, cudaFuncAttributeMaxDynamicSharedMemorySize, SMEM_TOTAL);

    convert_x_kernel<<<16384, 256>>>(X);
    convert_w_kernel<<<dim3(20, 128), dim3(32, 8)>>>(dw1, dd);
    convert_q_kernel<<<dim3(64, 4, 4), dim3(32, 8)>>>(qkw);

    gemm1_mma<<<dim3(5, 32), 256, SMEM_TOTAL>>>(out);
    gemm2_mma<<<dim3(16, 32, 4), 256, SMEM_TOTAL>>>(out);
    kw_kernel<<<BT, 256>>>(out);
}